// round 3
// baseline (speedup 1.0000x reference)
#include <cuda_runtime.h>
#include <math_constants.h>

// ---------------- problem constants ----------------
#define BB 8
#define CC 256
#define HW 4096                    // 64*64
#define PIXTOT (BB*HW)             // 32768
#define NSPLIT 8
#define CPB (CC/NSPLIT)            // 32 channels per block
#define T1 128                     // threads in main kernel
#define PIX 512                    // pixels per block (4 per thread)
#define PB_PER_B (HW/PIX)          // 8
#define HO2 65536                  // 256*256
#define KLPIX (BB*HO2)             // 524288

// ---------------- scratch (static device allocs are allowed) ----------------
// per-pixel partials per split: q: 0 sq_opt 1 cos_opt 2 sq_het 3 cos_het 4 s_sum 5 t_sum 6 s_max 7 t_max
__device__ __align__(16) float g_P[NSPLIT][8][PIXTOT];   // 8 MB
__device__ __align__(16) float g_chan_s[BB*CC];
__device__ __align__(16) float g_chan_t[BB*CC];
__device__ __align__(16) float g_od[PIXTOT];
__device__ __align__(16) float g_hd[PIXTOT];
__device__ __align__(16) float g_ssp[PIXTOT];
__device__ __align__(16) float g_tsp[PIXTOT];
// scalar accumulators:
// 0 gl_sum  1 loc_sum  3 od_sum  4 diff_sum  5 sp_sum  6 chf_sum  7 chl_sum  8 kl_sum  9 c1_sum
__device__ float g_acc[16];

// ---------------- helpers ----------------
__device__ __forceinline__ float warp_sum(float v) {
#pragma unroll
    for (int o = 16; o; o >>= 1) v += __shfl_xor_sync(0xffffffffu, v, o);
    return v;
}

__device__ __forceinline__ float sigm(float x) {
    return __fdividef(1.f, 1.f + __expf(-x));
}

// block reduce (256 threads max, 8 warps) of one value, returns on thread 0
__device__ __forceinline__ float block_sum_256(float v, float* smem8) {
    v = warp_sum(v);
    const int lane = threadIdx.x & 31;
    const int wid  = threadIdx.x >> 5;
    if (lane == 0) smem8[wid] = v;
    __syncthreads();
    float r = 0.f;
    if (threadIdx.x == 0) {
        const int nw = (blockDim.x + 31) >> 5;
        for (int i = 0; i < nw; i++) r += smem8[i];
    }
    __syncthreads();
    return r;
}

// ---------------- K0: zero accumulators ----------------
__global__ void k_init() {
    const int i = blockIdx.x * blockDim.x + threadIdx.x;
    if (i < 16) g_acc[i] = 0.f;
    if (i < BB * CC) { g_chan_s[i] = 0.f; g_chan_t[i] = 0.f; }
}

// ---------------- K1: the big streamer ----------------
__global__ __launch_bounds__(T1) void k_main(
    const float* __restrict__ S, const float* __restrict__ Tt,
    const float* __restrict__ O1, const float* __restrict__ O2,
    const float* __restrict__ SA, const float* __restrict__ M)
{
    const int b     = blockIdx.x >> 3;          // blockIdx.x = b*8 + pb
    const int pb    = blockIdx.x & 7;
    const int split = blockIdx.y;
    const int c0    = split * CPB;
    const int px    = pb * PIX + threadIdx.x * 4;   // pixel within batch (mult of 4)
    const size_t base = (size_t)b * CC * HW + (size_t)c0 * HW + px;

    const float4* sp  = (const float4*)(S  + base);
    const float4* tp  = (const float4*)(Tt + base);
    const float4* o1p = (const float4*)(O1 + base);
    const float4* o2p = (const float4*)(O2 + base);
    const float4* sap = (const float4*)(SA + base);

    float sqo[4] = {0,0,0,0}, cso[4] = {0,0,0,0};
    float sqh[4] = {0,0,0,0}, csh[4] = {0,0,0,0};
    float ssm[4] = {0,0,0,0}, tsm[4] = {0,0,0,0};
    float gl[4]  = {0,0,0,0};
    float smx[4] = {-CUDART_INF_F,-CUDART_INF_F,-CUDART_INF_F,-CUDART_INF_F};
    float tmx[4] = {-CUDART_INF_F,-CUDART_INF_F,-CUDART_INF_F,-CUDART_INF_F};

    const int lane = threadIdx.x & 31;

#pragma unroll 4
    for (int ci = 0; ci < CPB; ci++) {
        const int off = ci * (HW / 4);
        const float4 s  = sp[off];
        const float4 t  = tp[off];
        const float4 a  = o1p[off];
        const float4 b2 = o2p[off];
        const float4 c2 = sap[off];
        const float sv[4] = {s.x, s.y, s.z, s.w};
        const float tv[4] = {t.x, t.y, t.z, t.w};
        const float av[4] = {a.x, a.y, a.z, a.w};
        const float bv[4] = {b2.x, b2.y, b2.z, b2.w};
        const float cv[4] = {c2.x, c2.y, c2.z, c2.w};
#pragma unroll
        for (int k = 0; k < 4; k++) {
            const float d = sv[k] - tv[k];
            gl[k]  += d * d;
            ssm[k] += sv[k];
            tsm[k] += tv[k];
            smx[k] = fmaxf(smx[k], sv[k]);
            tmx[k] = fmaxf(tmx[k], tv[k]);
            const float d1 = av[k] - bv[k];
            sqo[k] += d1 * d1;
            const float x1 = av[k] * bv[k];
            cso[k] += __fdividef(x1, fmaxf(fabsf(x1), 1e-8f));
            const float d2 = av[k] - cv[k];
            sqh[k] += d2 * d2;
            const float x2 = av[k] * cv[k];
            csh[k] += __fdividef(x2, fmaxf(fabsf(x2), 1e-8f));
        }
        // channel means for s and t (sum over this warp's 128 pixels)
        float sred = warp_sum(sv[0] + sv[1] + sv[2] + sv[3]);
        float tred = warp_sum(tv[0] + tv[1] + tv[2] + tv[3]);
        if (lane == 0) {
            atomicAdd(&g_chan_s[b * CC + c0 + ci], sred);
            atomicAdd(&g_chan_t[b * CC + c0 + ci], tred);
        }
    }

    // store per-pixel partials (distinct per split -> no atomics)
    const int g4 = (b * HW + px) >> 2;
    ((float4*)g_P[split][0])[g4] = make_float4(sqo[0], sqo[1], sqo[2], sqo[3]);
    ((float4*)g_P[split][1])[g4] = make_float4(cso[0], cso[1], cso[2], cso[3]);
    ((float4*)g_P[split][2])[g4] = make_float4(sqh[0], sqh[1], sqh[2], sqh[3]);
    ((float4*)g_P[split][3])[g4] = make_float4(csh[0], csh[1], csh[2], csh[3]);
    ((float4*)g_P[split][4])[g4] = make_float4(ssm[0], ssm[1], ssm[2], ssm[3]);
    ((float4*)g_P[split][5])[g4] = make_float4(tsm[0], tsm[1], tsm[2], tsm[3]);
    ((float4*)g_P[split][6])[g4] = make_float4(smx[0], smx[1], smx[2], smx[3]);
    ((float4*)g_P[split][7])[g4] = make_float4(tmx[0], tmx[1], tmx[2], tmx[3]);

    // global / local (mask-weighted) feature-loss partials
    const float4 m4 = *(const float4*)(M + b * HW + px);
    const float mv[4] = {m4.x, m4.y, m4.z, m4.w};
    float glt = 0.f, loct = 0.f;
#pragma unroll
    for (int k = 0; k < 4; k++) { glt += gl[k]; loct += mv[k] * mv[k] * gl[k]; }

    __shared__ float smem8[8];
    glt = block_sum_256(glt, smem8);
    float loct_b = block_sum_256(loct, smem8);
    if (threadIdx.x == 0) {
        atomicAdd(&g_acc[0], glt);
        atomicAdd(&g_acc[1], loct_b);
    }
}

// ---------------- K2: finalize per-pixel maps, reduce sum(opt_diff) ----------------
__global__ void k_pix1() {
    const int p4 = blockIdx.x * blockDim.x + threadIdx.x;   // 0..8191 (float4 pixels)
    float sqo[4] = {0,0,0,0}, cso[4] = {0,0,0,0}, sqh[4] = {0,0,0,0}, csh[4] = {0,0,0,0};
    float ssm[4] = {0,0,0,0}, tsm[4] = {0,0,0,0};
    float smx[4] = {-CUDART_INF_F,-CUDART_INF_F,-CUDART_INF_F,-CUDART_INF_F};
    float tmx[4] = {-CUDART_INF_F,-CUDART_INF_F,-CUDART_INF_F,-CUDART_INF_F};
#pragma unroll
    for (int sp = 0; sp < NSPLIT; sp++) {
        float4 v;
        v = ((const float4*)g_P[sp][0])[p4]; sqo[0]+=v.x; sqo[1]+=v.y; sqo[2]+=v.z; sqo[3]+=v.w;
        v = ((const float4*)g_P[sp][1])[p4]; cso[0]+=v.x; cso[1]+=v.y; cso[2]+=v.z; cso[3]+=v.w;
        v = ((const float4*)g_P[sp][2])[p4]; sqh[0]+=v.x; sqh[1]+=v.y; sqh[2]+=v.z; sqh[3]+=v.w;
        v = ((const float4*)g_P[sp][3])[p4]; csh[0]+=v.x; csh[1]+=v.y; csh[2]+=v.z; csh[3]+=v.w;
        v = ((const float4*)g_P[sp][4])[p4]; ssm[0]+=v.x; ssm[1]+=v.y; ssm[2]+=v.z; ssm[3]+=v.w;
        v = ((const float4*)g_P[sp][5])[p4]; tsm[0]+=v.x; tsm[1]+=v.y; tsm[2]+=v.z; tsm[3]+=v.w;
        v = ((const float4*)g_P[sp][6])[p4]; smx[0]=fmaxf(smx[0],v.x); smx[1]=fmaxf(smx[1],v.y); smx[2]=fmaxf(smx[2],v.z); smx[3]=fmaxf(smx[3],v.w);
        v = ((const float4*)g_P[sp][7])[p4]; tmx[0]=fmaxf(tmx[0],v.x); tmx[1]=fmaxf(tmx[1],v.y); tmx[2]=fmaxf(tmx[2],v.z); tmx[3]=fmaxf(tmx[3],v.w);
    }
    float od[4], hd[4], spv[4], tpv[4];
    float od_local = 0.f;
#pragma unroll
    for (int k = 0; k < 4; k++) {
        const float l2o = sqrtf(sqo[k] + 1e-6f);
        const float co  = cso[k] * (1.f / 256.f);
        od[k] = (l2o + 1.f - co) * sigm(l2o * 5.f);
        const float l2h = sqrtf(sqh[k] + 1e-6f);
        const float ch  = csh[k] * (1.f / 256.f);
        hd[k] = (l2h + 1.f - ch) * sigm(l2h * 5.f);
        spv[k] = sigm(ssm[k] * (1.f / 256.f) + smx[k]);
        tpv[k] = sigm(tsm[k] * (1.f / 256.f) + tmx[k]);
        od_local += od[k];
    }
    ((float4*)g_od)[p4]  = make_float4(od[0], od[1], od[2], od[3]);
    ((float4*)g_hd)[p4]  = make_float4(hd[0], hd[1], hd[2], hd[3]);
    ((float4*)g_ssp)[p4] = make_float4(spv[0], spv[1], spv[2], spv[3]);
    ((float4*)g_tsp)[p4] = make_float4(tpv[0], tpv[1], tpv[2], tpv[3]);

    __shared__ float smem8[8];
    const float bs = block_sum_256(od_local, smem8);
    if (threadIdx.x == 0) atomicAdd(&g_acc[3], bs);
}

// ---------------- K3: masked diff / spatial / channel losses ----------------
__global__ void k_pix2() {
    const int p4 = blockIdx.x * blockDim.x + threadIdx.x;   // 0..8191
    const float mean_od = g_acc[3] * (1.f / 32768.f);
    const float thr = mean_od * 1.5f;
    const float aw = sigm(mean_od * 10.f);

    const float4 od4 = ((const float4*)g_od)[p4];
    const float4 hd4 = ((const float4*)g_hd)[p4];
    const float4 sp4 = ((const float4*)g_ssp)[p4];
    const float4 tp4 = ((const float4*)g_tsp)[p4];
    const float odv[4] = {od4.x, od4.y, od4.z, od4.w};
    const float hdv[4] = {hd4.x, hd4.y, hd4.z, hd4.w};
    const float spv[4] = {sp4.x, sp4.y, sp4.z, sp4.w};
    const float tpv[4] = {tp4.x, tp4.y, tp4.z, tp4.w};

    float dsum = 0.f, spsum = 0.f;
#pragma unroll
    for (int k = 0; k < 4; k++) {
        const float mask = (odv[k] > thr) ? 1.f : 0.f;
        const float w = mask * 2.f + (1.f - mask) * 0.5f;
        const float dd = hdv[k] * w - odv[k] * w;
        dsum += dd * dd;
        const float amp = 1.f + aw * mask;
        const float sd = spv[k] * amp - tpv[k] * amp;
        spsum += sd * sd;
    }

    float chf = 0.f, chl = 0.f;
    if (p4 < (BB * CC) / 4) {
        const float4 cs = ((const float4*)g_chan_s)[p4];
        const float4 ct = ((const float4*)g_chan_t)[p4];
        const float csv[4] = {cs.x, cs.y, cs.z, cs.w};
        const float ctv[4] = {ct.x, ct.y, ct.z, ct.w};
#pragma unroll
        for (int k = 0; k < 4; k++) {
            const float ms = csv[k] * (1.f / (float)HW);
            const float mt = ctv[k] * (1.f / (float)HW);
            const float d = ms - mt;
            chf += d * d;
            const float e = sigm(ms) - sigm(mt);
            chl += e * e;
        }
    }

    __shared__ float smem8[8];
    float r;
    r = block_sum_256(dsum, smem8);  if (threadIdx.x == 0) atomicAdd(&g_acc[4], r);
    r = block_sum_256(spsum, smem8); if (threadIdx.x == 0) atomicAdd(&g_acc[5], r);
    r = block_sum_256(chf, smem8);   if (threadIdx.x == 0) atomicAdd(&g_acc[6], r);
    r = block_sum_256(chl, smem8);   if (threadIdx.x == 0) atomicAdd(&g_acc[7], r);
}

// ---------------- K4: KL + class1 over outputs ----------------
__global__ void k_kl(const float* __restrict__ SO, const float* __restrict__ TO) {
    const int idx = blockIdx.x * blockDim.x + threadIdx.x;  // 0..131071
    const int b  = idx >> 14;           // 16384 float4s per batch row
    const int i4 = idx & 16383;
    const size_t base = (size_t)b * 32768 + i4;   // float4 units; batch stride = 2*65536/4

    const float4 s0 = ((const float4*)SO)[base];
    const float4 s1 = ((const float4*)SO)[base + 16384];
    const float4 t0 = ((const float4*)TO)[base];
    const float4 t1 = ((const float4*)TO)[base + 16384];
    const float s0v[4] = {s0.x, s0.y, s0.z, s0.w};
    const float s1v[4] = {s1.x, s1.y, s1.z, s1.w};
    const float t0v[4] = {t0.x, t0.y, t0.z, t0.w};
    const float t1v[4] = {t1.x, t1.y, t1.z, t1.w};

    float kls = 0.f, c1s = 0.f;
#pragma unroll
    for (int k = 0; k < 4; k++) {
        const float a0 = s0v[k] * 0.25f, a1 = s1v[k] * 0.25f;
        const float mx = fmaxf(a0, a1);
        const float lse = mx + __logf(__expf(a0 - mx) + __expf(a1 - mx));
        const float ls0 = a0 - lse, ls1 = a1 - lse;
        const float b0 = t0v[k] * 0.25f, b1 = t1v[k] * 0.25f;
        const float mt = fmaxf(b0, b1);
        const float e0 = __expf(b0 - mt), e1 = __expf(b1 - mt);
        const float Z = e0 + e1;
        const float lZ = __logf(Z);
        const float p0 = __fdividef(e0, Z), p1 = __fdividef(e1, Z);
        kls += p0 * ((b0 - mt - lZ) - ls0) + p1 * ((b1 - mt - lZ) - ls1);
        const float dd = __expf(ls1) - p1;
        c1s += dd * dd;
    }

    __shared__ float smem8[8];
    float r;
    r = block_sum_256(kls, smem8); if (threadIdx.x == 0) atomicAdd(&g_acc[8], r);
    r = block_sum_256(c1s, smem8); if (threadIdx.x == 0) atomicAdd(&g_acc[9], r);
}

// ---------------- K5: final combine ----------------
__global__ void k_final(float* out, int out_size) {
    if (threadIdx.x != 0 || blockIdx.x != 0) return;
    const float gl  = g_acc[0] * (1.f / 8388608.f);
    const float loc = g_acc[1] * (1.f / 8388608.f);
    const float chf = g_acc[6] * (1.f / 2048.f);
    const float feat = 0.3f * gl + 0.5f * loc + 0.2f * chf;

    const float kl  = g_acc[8] * 2.f;                 // (/B=8) * T^2=16
    const float c1  = g_acc[9] * (2.f / 524288.f);
    const float outl = kl + c1;

    const float mean_od = g_acc[3] * (1.f / 32768.f);
    const float aw = sigm(mean_od * 10.f);
    const float dif = g_acc[4] * (1.f / 32768.f);
    const float sp  = g_acc[5] * (1.f / 32768.f);
    const float chl = g_acc[7] * (1.f / 2048.f);
    const float alpha = 0.5f * (1.f + 0.5f * aw);
    const float beta  = 0.3f * (1.f - 0.3f * aw);
    const float gamma = 0.2f * (1.f + 0.5f * aw);
    const float datt = alpha * dif + beta * chl + gamma * sp;

    const float total = 0.3f * feat + 0.4f * outl + 0.3f * datt;
    if (out_size > 0) out[0] = total;
    if (out_size > 1) out[1] = feat;
    if (out_size > 2) out[2] = outl;
    if (out_size > 3) out[3] = datt;
}

// ---------------- launch ----------------
extern "C" void kernel_launch(void* const* d_in, const int* in_sizes, int n_in,
                              void* d_out, int out_size) {
    const float* S  = (const float*)d_in[0];   // student_features
    const float* Tt = (const float*)d_in[1];   // teacher_features
    const float* SO = (const float*)d_in[2];   // student_outputs
    const float* TO = (const float*)d_in[3];   // teacher_outputs
    const float* O1 = (const float*)d_in[4];   // opt_t1
    const float* O2 = (const float*)d_in[5];   // opt_t2
    const float* SA = (const float*)d_in[6];   // sar_t2
    const float* M  = (const float*)d_in[7];   // feature_mask
    (void)in_sizes; (void)n_in;

    k_init<<<8, 256>>>();
    dim3 g1(BB * PB_PER_B, NSPLIT);            // (64, 8) = 512 blocks
    k_main<<<g1, T1>>>(S, Tt, O1, O2, SA, M);
    k_kl<<<512, 256>>>(SO, TO);
    k_pix1<<<32, 256>>>();
    k_pix2<<<32, 256>>>();
    k_final<<<1, 32>>>((float*)d_out, out_size);
}

// round 4
// speedup vs baseline: 1.3591x; 1.3591x over previous
#include <cuda_runtime.h>
#include <math_constants.h>

// ---------------- problem constants ----------------
#define BB 8
#define CC 256
#define HW 4096                    // 64*64
#define PIXTOT (BB*HW)             // 32768
#define NSPLIT 8
#define CPB (CC/NSPLIT)            // 32 channels per block
#define T1 128                     // threads in fused kernel
#define PIX 512                    // pixels per main block (4 per thread)
#define MAIN_BLOCKS 512            // 8 batches * 8 pixel-blocks * 8 splits
#define KL_BLOCKS 512              // 512 blocks * 128 thr * 2 idx = 131072 float4-pairs
#define HO2 65536                  // 256*256

// ---------------- scratch ----------------
// per-pixel partials per split: q: 0 sq_opt 1 cos_opt 2 sq_het 3 cos_het 4 s_sum 5 t_sum 6 s_max 7 t_max
__device__ __align__(16) float g_P[NSPLIT][8][PIXTOT];   // 8 MB
__device__ __align__(16) float g_chan_s[BB*CC];
__device__ __align__(16) float g_chan_t[BB*CC];
__device__ __align__(16) float g_od[PIXTOT];
__device__ __align__(16) float g_hd[PIXTOT];
__device__ __align__(16) float g_ssp[PIXTOT];
__device__ __align__(16) float g_tsp[PIXTOT];
// 0 gl_sum 1 loc_sum 3 od_sum 4 diff_sum 5 sp_sum 6 chf_sum 7 chl_sum 8 kl_sum 9 c1_sum
__device__ float g_acc[16];
__device__ unsigned g_cnt;

// ---------------- helpers ----------------
__device__ __forceinline__ float warp_sum(float v) {
#pragma unroll
    for (int o = 16; o; o >>= 1) v += __shfl_xor_sync(0xffffffffu, v, o);
    return v;
}

__device__ __forceinline__ float sigm(float x) {
    return __fdividef(1.f, 1.f + __expf(-x));
}

// cos term: x / max(|x|, 1e-8)  ==  sign(x) when |x|>=1e-8, else x*1e8 (no MUFU)
__device__ __forceinline__ float cos_term(float a, float b) {
    const float x = a * b;
    const float s = __uint_as_float((__float_as_uint(x) & 0x80000000u) | 0x3f800000u);
    return (fabsf(x) >= 1e-8f) ? s : x * 1e8f;
}

// block reduce (<=256 threads, 8 warps) -> value on thread 0
__device__ __forceinline__ float block_sum(float v, float* smem8) {
    v = warp_sum(v);
    const int lane = threadIdx.x & 31;
    const int wid  = threadIdx.x >> 5;
    if (lane == 0) smem8[wid] = v;
    __syncthreads();
    float r = 0.f;
    if (threadIdx.x == 0) {
        const int nw = (blockDim.x + 31) >> 5;
        for (int i = 0; i < nw; i++) r += smem8[i];
    }
    __syncthreads();
    return r;
}

// ---------------- K0: zero accumulators ----------------
__global__ void k_init() {
    const int i = blockIdx.x * blockDim.x + threadIdx.x;
    if (i < 16) g_acc[i] = 0.f;
    if (i == 16) g_cnt = 0u;
    if (i < BB * CC) { g_chan_s[i] = 0.f; g_chan_t[i] = 0.f; }
}

// ---------------- K1: fused big streamer (features/diff) + KL ----------------
__global__ __launch_bounds__(T1) void k_fused(
    const float* __restrict__ S, const float* __restrict__ Tt,
    const float* __restrict__ O1, const float* __restrict__ O2,
    const float* __restrict__ SA, const float* __restrict__ M,
    const float* __restrict__ SO, const float* __restrict__ TO)
{
    __shared__ float smem8[8];

    if (blockIdx.x < MAIN_BLOCKS) {
        // ---- main streamer role ----
        const int blk   = blockIdx.x;
        const int split = blk >> 6;           // 0..7
        const int rem   = blk & 63;
        const int b     = rem >> 3;           // 0..7
        const int pb    = rem & 7;            // 0..7
        const int c0    = split * CPB;
        const int px    = pb * PIX + threadIdx.x * 4;   // pixel within batch
        const size_t base = (size_t)b * CC * HW + (size_t)c0 * HW + px;

        const float4* sp  = (const float4*)(S  + base);
        const float4* tp  = (const float4*)(Tt + base);
        const float4* o1p = (const float4*)(O1 + base);
        const float4* o2p = (const float4*)(O2 + base);
        const float4* sap = (const float4*)(SA + base);

        float sqo[4] = {0,0,0,0}, cso[4] = {0,0,0,0};
        float sqh[4] = {0,0,0,0}, csh[4] = {0,0,0,0};
        float ssm[4] = {0,0,0,0}, tsm[4] = {0,0,0,0};
        float gl[4]  = {0,0,0,0};
        float smx[4] = {-CUDART_INF_F,-CUDART_INF_F,-CUDART_INF_F,-CUDART_INF_F};
        float tmx[4] = {-CUDART_INF_F,-CUDART_INF_F,-CUDART_INF_F,-CUDART_INF_F};

        const int lane = threadIdx.x & 31;

#pragma unroll 8
        for (int ci = 0; ci < CPB; ci++) {
            const int off = ci * (HW / 4);
            const float4 s  = sp[off];
            const float4 t  = tp[off];
            const float4 a  = o1p[off];
            const float4 b2 = o2p[off];
            const float4 c2 = sap[off];
            const float sv[4] = {s.x, s.y, s.z, s.w};
            const float tv[4] = {t.x, t.y, t.z, t.w};
            const float av[4] = {a.x, a.y, a.z, a.w};
            const float bv[4] = {b2.x, b2.y, b2.z, b2.w};
            const float cv[4] = {c2.x, c2.y, c2.z, c2.w};
#pragma unroll
            for (int k = 0; k < 4; k++) {
                const float d = sv[k] - tv[k];
                gl[k]  += d * d;
                ssm[k] += sv[k];
                tsm[k] += tv[k];
                smx[k] = fmaxf(smx[k], sv[k]);
                tmx[k] = fmaxf(tmx[k], tv[k]);
                const float d1 = av[k] - bv[k];
                sqo[k] += d1 * d1;
                cso[k] += cos_term(av[k], bv[k]);
                const float d2 = av[k] - cv[k];
                sqh[k] += d2 * d2;
                csh[k] += cos_term(av[k], cv[k]);
            }
            // per-channel sums over this warp's 128 pixels
            float sred = warp_sum(sv[0] + sv[1] + sv[2] + sv[3]);
            float tred = warp_sum(tv[0] + tv[1] + tv[2] + tv[3]);
            if (lane == 0) {
                atomicAdd(&g_chan_s[b * CC + c0 + ci], sred);
                atomicAdd(&g_chan_t[b * CC + c0 + ci], tred);
            }
        }

        const int g4 = (b * HW + px) >> 2;
        ((float4*)g_P[split][0])[g4] = make_float4(sqo[0], sqo[1], sqo[2], sqo[3]);
        ((float4*)g_P[split][1])[g4] = make_float4(cso[0], cso[1], cso[2], cso[3]);
        ((float4*)g_P[split][2])[g4] = make_float4(sqh[0], sqh[1], sqh[2], sqh[3]);
        ((float4*)g_P[split][3])[g4] = make_float4(csh[0], csh[1], csh[2], csh[3]);
        ((float4*)g_P[split][4])[g4] = make_float4(ssm[0], ssm[1], ssm[2], ssm[3]);
        ((float4*)g_P[split][5])[g4] = make_float4(tsm[0], tsm[1], tsm[2], tsm[3]);
        ((float4*)g_P[split][6])[g4] = make_float4(smx[0], smx[1], smx[2], smx[3]);
        ((float4*)g_P[split][7])[g4] = make_float4(tmx[0], tmx[1], tmx[2], tmx[3]);

        const float4 m4 = *(const float4*)(M + b * HW + px);
        const float mv[4] = {m4.x, m4.y, m4.z, m4.w};
        float glt = 0.f, loct = 0.f;
#pragma unroll
        for (int k = 0; k < 4; k++) { glt += gl[k]; loct += mv[k] * mv[k] * gl[k]; }

        glt = block_sum(glt, smem8);
        const float loct_b = block_sum(loct, smem8);
        if (threadIdx.x == 0) {
            atomicAdd(&g_acc[0], glt);
            atomicAdd(&g_acc[1], loct_b);
        }
    } else {
        // ---- KL role ----
        const int kid = blockIdx.x - MAIN_BLOCKS;   // 0..511
        float kls = 0.f, c1s = 0.f;
#pragma unroll
        for (int it = 0; it < 2; it++) {
            const int idx = kid * 256 + it * 128 + threadIdx.x;   // 0..131071
            const int b  = idx >> 14;
            const int i4 = idx & 16383;
            const size_t base = (size_t)b * 32768 + i4;

            const float4 s0 = ((const float4*)SO)[base];
            const float4 s1 = ((const float4*)SO)[base + 16384];
            const float4 t0 = ((const float4*)TO)[base];
            const float4 t1 = ((const float4*)TO)[base + 16384];
            const float s0v[4] = {s0.x, s0.y, s0.z, s0.w};
            const float s1v[4] = {s1.x, s1.y, s1.z, s1.w};
            const float t0v[4] = {t0.x, t0.y, t0.z, t0.w};
            const float t1v[4] = {t1.x, t1.y, t1.z, t1.w};
#pragma unroll
            for (int k = 0; k < 4; k++) {
                const float a0 = s0v[k] * 0.25f, a1 = s1v[k] * 0.25f;
                const float mx = fmaxf(a0, a1);
                const float lse = mx + __logf(__expf(a0 - mx) + __expf(a1 - mx));
                const float ls0 = a0 - lse, ls1 = a1 - lse;
                const float b0 = t0v[k] * 0.25f, b1 = t1v[k] * 0.25f;
                const float mt = fmaxf(b0, b1);
                const float e0 = __expf(b0 - mt), e1 = __expf(b1 - mt);
                const float Z = e0 + e1;
                const float lZ = __logf(Z);
                const float rz = __fdividef(1.f, Z);
                const float p0 = e0 * rz, p1 = e1 * rz;
                kls += p0 * ((b0 - mt - lZ) - ls0) + p1 * ((b1 - mt - lZ) - ls1);
                const float dd = __expf(ls1) - p1;
                c1s += dd * dd;
            }
        }
        float r = block_sum(kls, smem8);
        if (threadIdx.x == 0) atomicAdd(&g_acc[8], r);
        r = block_sum(c1s, smem8);
        if (threadIdx.x == 0) atomicAdd(&g_acc[9], r);
    }
}

// ---------------- K2: finalize per-pixel maps (thread per scalar pixel) ----------------
__global__ __launch_bounds__(256) void k_pix1() {
    const int pix = blockIdx.x * 256 + threadIdx.x;   // 0..32767, 128 blocks
    float sqo = 0.f, cso = 0.f, sqh = 0.f, csh = 0.f, ssm = 0.f, tsm = 0.f;
    float smx = -CUDART_INF_F, tmx = -CUDART_INF_F;
#pragma unroll
    for (int sp = 0; sp < NSPLIT; sp++) {
        sqo += g_P[sp][0][pix];
        cso += g_P[sp][1][pix];
        sqh += g_P[sp][2][pix];
        csh += g_P[sp][3][pix];
        ssm += g_P[sp][4][pix];
        tsm += g_P[sp][5][pix];
        smx = fmaxf(smx, g_P[sp][6][pix]);
        tmx = fmaxf(tmx, g_P[sp][7][pix]);
    }
    const float l2o = sqrtf(sqo + 1e-6f);
    const float od  = (l2o + 1.f - cso * (1.f / 256.f)) * sigm(l2o * 5.f);
    const float l2h = sqrtf(sqh + 1e-6f);
    const float hd  = (l2h + 1.f - csh * (1.f / 256.f)) * sigm(l2h * 5.f);
    g_od[pix]  = od;
    g_hd[pix]  = hd;
    g_ssp[pix] = sigm(ssm * (1.f / 256.f) + smx);
    g_tsp[pix] = sigm(tsm * (1.f / 256.f) + tmx);

    __shared__ float smem8[8];
    const float bs = block_sum(od, smem8);
    if (threadIdx.x == 0) atomicAdd(&g_acc[3], bs);
}

// ---------------- K3: masked losses + (last block) final combine ----------------
__global__ __launch_bounds__(256) void k_pix2_final(float* out, int out_size) {
    const int p4 = blockIdx.x * 256 + threadIdx.x;   // 0..8191 (32 blocks)
    const float mean_od = g_acc[3] * (1.f / 32768.f);
    const float thr = mean_od * 1.5f;
    const float aw = sigm(mean_od * 10.f);

    const float4 od4 = ((const float4*)g_od)[p4];
    const float4 hd4 = ((const float4*)g_hd)[p4];
    const float4 sp4 = ((const float4*)g_ssp)[p4];
    const float4 tp4 = ((const float4*)g_tsp)[p4];
    const float odv[4] = {od4.x, od4.y, od4.z, od4.w};
    const float hdv[4] = {hd4.x, hd4.y, hd4.z, hd4.w};
    const float spv[4] = {sp4.x, sp4.y, sp4.z, sp4.w};
    const float tpv[4] = {tp4.x, tp4.y, tp4.z, tp4.w};

    float dsum = 0.f, spsum = 0.f;
#pragma unroll
    for (int k = 0; k < 4; k++) {
        const float mask = (odv[k] > thr) ? 1.f : 0.f;
        const float w = mask * 2.f + (1.f - mask) * 0.5f;
        const float dd = hdv[k] * w - odv[k] * w;
        dsum += dd * dd;
        const float amp = 1.f + aw * mask;
        const float sd = spv[k] * amp - tpv[k] * amp;
        spsum += sd * sd;
    }

    float chf = 0.f, chl = 0.f;
    if (p4 < (BB * CC) / 4) {
        const float4 cs = ((const float4*)g_chan_s)[p4];
        const float4 ct = ((const float4*)g_chan_t)[p4];
        const float csv[4] = {cs.x, cs.y, cs.z, cs.w};
        const float ctv[4] = {ct.x, ct.y, ct.z, ct.w};
#pragma unroll
        for (int k = 0; k < 4; k++) {
            const float ms = csv[k] * (1.f / (float)HW);
            const float mt = ctv[k] * (1.f / (float)HW);
            const float d = ms - mt;
            chf += d * d;
            const float e = sigm(ms) - sigm(mt);
            chl += e * e;
        }
    }

    __shared__ float smem8[8];
    float r;
    r = block_sum(dsum, smem8);  if (threadIdx.x == 0) atomicAdd(&g_acc[4], r);
    r = block_sum(spsum, smem8); if (threadIdx.x == 0) atomicAdd(&g_acc[5], r);
    r = block_sum(chf, smem8);   if (threadIdx.x == 0) atomicAdd(&g_acc[6], r);
    r = block_sum(chl, smem8);   if (threadIdx.x == 0) atomicAdd(&g_acc[7], r);

    // last-block final combine
    __shared__ bool isLast;
    __threadfence();
    if (threadIdx.x == 0) {
        const unsigned old = atomicAdd(&g_cnt, 1u);
        isLast = (old == gridDim.x - 1);
    }
    __syncthreads();
    if (isLast && threadIdx.x == 0) {
        volatile float* A = g_acc;   // bypass stale L1 (g_acc line was loaded above)
        const float gl  = A[0] * (1.f / 8388608.f);
        const float loc = A[1] * (1.f / 8388608.f);
        const float chfv = A[6] * (1.f / 2048.f);
        const float feat = 0.3f * gl + 0.5f * loc + 0.2f * chfv;

        const float kl  = A[8] * 2.f;                 // (/B=8) * T^2=16
        const float c1  = A[9] * (2.f / 524288.f);
        const float outl = kl + c1;

        const float mo  = A[3] * (1.f / 32768.f);
        const float awf = sigm(mo * 10.f);
        const float dif = A[4] * (1.f / 32768.f);
        const float sp  = A[5] * (1.f / 32768.f);
        const float chlv = A[7] * (1.f / 2048.f);
        const float alpha = 0.5f * (1.f + 0.5f * awf);
        const float beta  = 0.3f * (1.f - 0.3f * awf);
        const float gamma = 0.2f * (1.f + 0.5f * awf);
        const float datt = alpha * dif + beta * chlv + gamma * sp;

        const float total = 0.3f * feat + 0.4f * outl + 0.3f * datt;
        if (out_size > 0) out[0] = total;
        if (out_size > 1) out[1] = feat;
        if (out_size > 2) out[2] = outl;
        if (out_size > 3) out[3] = datt;
    }
}

// ---------------- launch ----------------
extern "C" void kernel_launch(void* const* d_in, const int* in_sizes, int n_in,
                              void* d_out, int out_size) {
    const float* S  = (const float*)d_in[0];   // student_features
    const float* Tt = (const float*)d_in[1];   // teacher_features
    const float* SO = (const float*)d_in[2];   // student_outputs
    const float* TO = (const float*)d_in[3];   // teacher_outputs
    const float* O1 = (const float*)d_in[4];   // opt_t1
    const float* O2 = (const float*)d_in[5];   // opt_t2
    const float* SA = (const float*)d_in[6];   // sar_t2
    const float* M  = (const float*)d_in[7];   // feature_mask
    (void)in_sizes; (void)n_in;

    k_init<<<8, 256>>>();
    k_fused<<<MAIN_BLOCKS + KL_BLOCKS, T1>>>(S, Tt, O1, O2, SA, M, SO, TO);
    k_pix1<<<PIXTOT / 256, 256>>>();
    k_pix2_final<<<32, 256>>>((float*)d_out, out_size);
}